// round 1
// baseline (speedup 1.0000x reference)
#include <cuda_runtime.h>
#include <math.h>

#define D_RF   2048
#define NOBS   20000
#define N_ST   1024
#define N_ACT  64
#define SDIM   256
#define DECAYF 0.9f
#define BETA_O 1.0f
#define BETA_S 1.0f

// ---- scratch (static device globals: no allocation) ----
__device__ float g_cosQ[D_RF * N_ST];   // 8 MB
__device__ float g_sinQ[D_RF * N_ST];   // 8 MB
__device__ float g_s0re[D_RF], g_s0im[D_RF];
__device__ float g_s1re[D_RF], g_s1im[D_RF];
__device__ float g_s2re[D_RF], g_s2im[D_RF];
__device__ float g_score[N_ST];
__device__ float g_dotRe;
__device__ float g_obsacc[NOBS];

// ============================================================
// Kernel AB (fused): blocks [0,512): theta=W@Q tiles -> cos/sin tables
//                    blocks [512,2560): state0 = M @ obs  (row dot)
//                    side duty: zero-init accumulators for this step
// ============================================================
__global__ void __launch_bounds__(256) k_ab(
    const float* __restrict__ W, const float* __restrict__ Q,
    const float* __restrict__ M_re, const float* __restrict__ M_im,
    const float* __restrict__ obs)
{
    __shared__ float sh[2 * 16 * 68];   // Ws[16][68] + Qs[16][68]; also reduction scratch
    const int b   = blockIdx.x;
    const int tid = threadIdx.x;

    if (b < 512) {
        // ---- phi_Q GEMM: 64x64 tile, 256 threads, 4x4 micro-tile ----
        float (*Ws)[68] = (float(*)[68])sh;
        float (*Qs)[68] = (float(*)[68])(sh + 16 * 68);
        const int td = b >> 4, ts = b & 15;
        const int d0 = td * 64, s0 = ts * 64;
        const int tx = tid & 15, ty = tid >> 4;

        float acc[4][4];
        #pragma unroll
        for (int i = 0; i < 4; i++)
            #pragma unroll
            for (int j = 0; j < 4; j++) acc[i][j] = 0.f;

        const int wdl = tid >> 2, wkq = (tid & 3) * 4;   // W loader: 4 threads/row
        const int qk  = tid >> 4, qsq = (tid & 15) * 4;  // Q loader

        for (int k0 = 0; k0 < SDIM; k0 += 16) {
            float4 w4 = *(const float4*)&W[(size_t)(d0 + wdl) * SDIM + k0 + wkq];
            float4 q4 = *(const float4*)&Q[(size_t)(k0 + qk) * N_ST + s0 + qsq];
            __syncthreads();
            Ws[wkq + 0][wdl] = w4.x; Ws[wkq + 1][wdl] = w4.y;
            Ws[wkq + 2][wdl] = w4.z; Ws[wkq + 3][wdl] = w4.w;
            *(float4*)&Qs[qk][qsq] = q4;
            __syncthreads();
            #pragma unroll
            for (int k = 0; k < 16; k++) {
                float4 wv = *(float4*)&Ws[k][ty * 4];
                float4 qv = *(float4*)&Qs[k][tx * 4];
                float wa[4] = {wv.x, wv.y, wv.z, wv.w};
                float qa[4] = {qv.x, qv.y, qv.z, qv.w};
                #pragma unroll
                for (int i = 0; i < 4; i++)
                    #pragma unroll
                    for (int j = 0; j < 4; j++)
                        acc[i][j] = fmaf(wa[i], qa[j], acc[i][j]);
            }
        }
        // epilogue: sincos + float4 stores
        #pragma unroll
        for (int i = 0; i < 4; i++) {
            float c[4], s[4];
            #pragma unroll
            for (int j = 0; j < 4; j++) __sincosf(acc[i][j], &s[j], &c[j]);
            size_t base = (size_t)(d0 + ty * 4 + i) * N_ST + s0 + tx * 4;
            *(float4*)&g_cosQ[base] = make_float4(c[0], c[1], c[2], c[3]);
            *(float4*)&g_sinQ[base] = make_float4(s[0], s[1], s[2], s[3]);
        }
    } else {
        const int d = b - 512;  // row of M, 0..2047
        // zero-init side duties (safe: consumers run in later launches)
        if (d < 80) { int o = d * 256 + tid; if (o < NOBS) g_obsacc[o] = 0.f; }
        if (d < 4)  g_score[d * 256 + tid] = 0.f;
        if (d == 0 && tid == 0) g_dotRe = 0.f;

        const float4* mr = (const float4*)(M_re + (size_t)d * NOBS);
        const float4* mi = (const float4*)(M_im + (size_t)d * NOBS);
        const float4* ob = (const float4*)obs;
        float are = 0.f, aim = 0.f;
        for (int i = tid; i < NOBS / 4; i += 256) {
            float4 o4 = ob[i]; float4 r4 = mr[i]; float4 i4 = mi[i];
            are += r4.x * o4.x + r4.y * o4.y + r4.z * o4.z + r4.w * o4.w;
            aim += i4.x * o4.x + i4.y * o4.y + i4.z * o4.z + i4.w * o4.w;
        }
        #pragma unroll
        for (int off = 16; off > 0; off >>= 1) {
            are += __shfl_down_sync(~0u, are, off);
            aim += __shfl_down_sync(~0u, aim, off);
        }
        const int w = tid >> 5, l = tid & 31;
        if (l == 0) { sh[w] = are; sh[8 + w] = aim; }
        __syncthreads();
        if (w == 0) {
            are = (l < 8) ? sh[l]     : 0.f;
            aim = (l < 8) ? sh[8 + l] : 0.f;
            #pragma unroll
            for (int off = 4; off > 0; off >>= 1) {
                are += __shfl_down_sync(~0u, are, off);
                aim += __shfl_down_sync(~0u, aim, off);
            }
            if (l == 0) { g_s0re[d] = are; g_s0im[d] = aim; }
        }
    }
}

// ============================================================
// Kernel C: v = V@action; theta_v = W@v; state1 = state0 * exp(i theta_v)
// grid 64 blocks x 256 threads: 32 W-rows per block (warp per row, 4 rows)
// ============================================================
__global__ void __launch_bounds__(256) k_state1(
    const float* __restrict__ V, const float* __restrict__ W,
    const float* __restrict__ action)
{
    __shared__ float vs[SDIM];
    const int tid = threadIdx.x;
    {   // v[tid] = dot(V[tid,:], action)   (cheap, duplicated per block)
        float a = 0.f;
        const float* vr = V + tid * N_ACT;
        #pragma unroll 8
        for (int k = 0; k < N_ACT; k++) a = fmaf(vr[k], action[k], a);
        vs[tid] = a;
    }
    __syncthreads();
    const int w = tid >> 5, l = tid & 31;
    #pragma unroll
    for (int r = 0; r < 4; r++) {
        const int d = blockIdx.x * 32 + w * 4 + r;
        const float* wr = W + (size_t)d * SDIM;
        float t = 0.f;
        #pragma unroll
        for (int k = l; k < SDIM; k += 32) t = fmaf(wr[k], vs[k], t);
        #pragma unroll
        for (int off = 16; off > 0; off >>= 1) t += __shfl_down_sync(~0u, t, off);
        if (l == 0) {
            float sn, cs;
            sincosf(t, &sn, &cs);   // precise: only 2048 calls
            const float a = g_s0re[d], bb = g_s0im[d];
            g_s1re[d] = a * cs - bb * sn;
            g_s1im[d] = a * sn + bb * cs;
        }
    }
}

// ============================================================
// Kernel D: score[s] += sum_d cosQ[d,s]*s1re[d] + sinQ[d,s]*s1im[d]
// grid 64: 4 s-chunks(256) x 16 d-chunks(128), atomicAdd partials
// ============================================================
__global__ void __launch_bounds__(256) k_score()
{
    __shared__ float s1r[128], s1i[128];
    const int sc = blockIdx.x & 3, dc = blockIdx.x >> 2;
    const int tid = threadIdx.x;
    const int d0 = dc * 128;
    if (tid < 128) { s1r[tid] = g_s1re[d0 + tid]; s1i[tid] = g_s1im[d0 + tid]; }
    __syncthreads();
    const int s = sc * 256 + tid;
    float acc = 0.f;
    #pragma unroll 4
    for (int dd = 0; dd < 128; dd++) {
        const size_t idx = (size_t)(d0 + dd) * N_ST + s;
        acc = fmaf(g_cosQ[idx], s1r[dd], acc);
        acc = fmaf(g_sinQ[idx], s1i[dd], acc);
    }
    atomicAdd(&g_score[s], acc * (BETA_S / (float)D_RF));
}

// ============================================================
// Kernel E: weights = softmax(score), 1 block x 1024 threads
// ============================================================
__global__ void __launch_bounds__(1024) k_weights()
{
    __shared__ float red[33];
    const int tid = threadIdx.x;
    const float v = g_score[tid];
    float m = v;
    #pragma unroll
    for (int off = 16; off > 0; off >>= 1) m = fmaxf(m, __shfl_xor_sync(~0u, m, off));
    if ((tid & 31) == 0) red[tid >> 5] = m;
    __syncthreads();
    if (tid < 32) {
        float t = red[tid];
        #pragma unroll
        for (int off = 16; off > 0; off >>= 1) t = fmaxf(t, __shfl_xor_sync(~0u, t, off));
        if (tid == 0) red[32] = t;
    }
    __syncthreads();
    const float mx = red[32];
    float e = __expf(v - mx);
    __syncthreads();
    float s = e;
    #pragma unroll
    for (int off = 16; off > 0; off >>= 1) s += __shfl_xor_sync(~0u, s, off);
    if ((tid & 31) == 0) red[tid >> 5] = s;
    __syncthreads();
    if (tid < 32) {
        float t = red[tid];
        #pragma unroll
        for (int off = 16; off > 0; off >>= 1) t += __shfl_xor_sync(~0u, t, off);
        if (tid == 0) red[32] = t;
    }
    __syncthreads();
    g_score[tid] = e / red[32];   // reuse g_score as weights storage
}

// ============================================================
// Kernel F: state2 = phi_Q @ weights; dotRe = Re(state0 . conj(state2))
// grid 256 x 256 threads: warp per row (8 rows/block)
// ============================================================
__global__ void __launch_bounds__(256) k_state2()
{
    __shared__ float ws[N_ST];
    const int tid = threadIdx.x;
    #pragma unroll
    for (int i = 0; i < 4; i++) ws[tid + i * 256] = g_score[tid + i * 256];
    __syncthreads();
    const int w = tid >> 5, l = tid & 31;
    const int d = blockIdx.x * 8 + w;
    const float* cr = g_cosQ + (size_t)d * N_ST;
    const float* si = g_sinQ + (size_t)d * N_ST;
    float ar = 0.f, ai = 0.f;
    #pragma unroll 4
    for (int s = l; s < N_ST; s += 32) {
        const float wt = ws[s];
        ar = fmaf(cr[s], wt, ar);
        ai = fmaf(si[s], wt, ai);
    }
    #pragma unroll
    for (int off = 16; off > 0; off >>= 1) {
        ar += __shfl_down_sync(~0u, ar, off);
        ai += __shfl_down_sync(~0u, ai, off);
    }
    if (l == 0) {
        g_s2re[d] = ar; g_s2im[d] = ai;
        atomicAdd(&g_dotRe, g_s0re[d] * ar + g_s0im[d] * ai);
    }
}

// ============================================================
// Kernel H: obsacc[o] += sum_d M_re[d,o]*s2re[d] + M_im[d,o]*s2im[d]
// grid 320: 40 o-chunks (512 obs as float2) x 8 d-chunks (256)
// ============================================================
__global__ void __launch_bounds__(256) k_obs(
    const float* __restrict__ M_re, const float* __restrict__ M_im)
{
    __shared__ float s2r[256], s2i[256];
    const int oc = blockIdx.x % 40, dc = blockIdx.x / 40;
    const int tid = threadIdx.x;
    const int d0 = dc * 256;
    s2r[tid] = g_s2re[d0 + tid];
    s2i[tid] = g_s2im[d0 + tid];
    __syncthreads();
    const int o2 = oc * 256 + tid;          // float2 index
    if (o2 >= NOBS / 2) return;
    const float2* mr = (const float2*)M_re;
    const float2* mi = (const float2*)M_im;
    float ax = 0.f, ay = 0.f;
    #pragma unroll 4
    for (int dd = 0; dd < 256; dd++) {
        const size_t row = (size_t)(d0 + dd) * (NOBS / 2) + o2;
        const float2 r = mr[row], im = mi[row];
        const float a = s2r[dd], b = s2i[dd];
        ax = fmaf(r.x, a, fmaf(im.x, b, ax));
        ay = fmaf(r.y, a, fmaf(im.y, b, ay));
    }
    atomicAdd(&g_obsacc[o2 * 2 + 0], ax);
    atomicAdd(&g_obsacc[o2 * 2 + 1], ay);
}

// ============================================================
// Kernel I: final = softmax( (BETA_O/D) * (DECAY*obsacc + obs*dotRe) )
// 1 block x 1024 threads, three passes over 20000 (L2-resident)
// ============================================================
__global__ void __launch_bounds__(1024) k_final(
    const float* __restrict__ obs, float* __restrict__ out)
{
    __shared__ float red[33];
    const int tid = threadIdx.x;
    const float dot   = g_dotRe;
    const float scale = BETA_O / (float)D_RF;

    float m = -1e30f;
    for (int i = tid; i < NOBS; i += 1024) {
        const float v = scale * (DECAYF * g_obsacc[i] + obs[i] * dot);
        g_obsacc[i] = v;
        m = fmaxf(m, v);
    }
    #pragma unroll
    for (int off = 16; off > 0; off >>= 1) m = fmaxf(m, __shfl_xor_sync(~0u, m, off));
    if ((tid & 31) == 0) red[tid >> 5] = m;
    __syncthreads();
    if (tid < 32) {
        float t = red[tid];
        #pragma unroll
        for (int off = 16; off > 0; off >>= 1) t = fmaxf(t, __shfl_xor_sync(~0u, t, off));
        if (tid == 0) red[32] = t;
    }
    __syncthreads();
    const float mx = red[32];
    __syncthreads();

    float s = 0.f;
    for (int i = tid; i < NOBS; i += 1024) {
        const float e = __expf(g_obsacc[i] - mx);
        g_obsacc[i] = e;
        s += e;
    }
    #pragma unroll
    for (int off = 16; off > 0; off >>= 1) s += __shfl_xor_sync(~0u, s, off);
    if ((tid & 31) == 0) red[tid >> 5] = s;
    __syncthreads();
    if (tid < 32) {
        float t = red[tid];
        #pragma unroll
        for (int off = 16; off > 0; off >>= 1) t += __shfl_xor_sync(~0u, t, off);
        if (tid == 0) red[32] = t;
    }
    __syncthreads();
    const float inv = 1.f / red[32];
    for (int i = tid; i < NOBS; i += 1024) out[i] = g_obsacc[i] * inv;
}

// ============================================================
extern "C" void kernel_launch(void* const* d_in, const int* in_sizes, int n_in,
                              void* d_out, int out_size)
{
    const float* Q      = (const float*)d_in[0];
    const float* V      = (const float*)d_in[1];
    const float* W      = (const float*)d_in[2];
    const float* M_re   = (const float*)d_in[3];
    const float* M_im   = (const float*)d_in[4];
    const float* obs    = (const float*)d_in[5];
    const float* action = (const float*)d_in[6];
    float* out = (float*)d_out;

    k_ab<<<2560, 256>>>(W, Q, M_re, M_im, obs);   // phi_Q tables + state0 + zero-init
    k_state1<<<64, 256>>>(V, W, action);          // v, theta_v, state1
    k_score<<<64, 256>>>();                       // state score partials
    k_weights<<<1, 1024>>>();                     // softmax -> weights (in g_score)
    k_state2<<<256, 256>>>();                     // state2 + dotRe
    k_obs<<<320, 256>>>(M_re, M_im);              // M^T . conj(state2) partials
    k_final<<<1, 1024>>>(obs, out);               // combine + softmax -> out
}

// round 2
// speedup vs baseline: 1.1733x; 1.1733x over previous
#include <cuda_runtime.h>
#include <math.h>

#define D_RF   2048
#define NOBS   20000
#define N_ST   1024
#define N_ACT  64
#define SDIM   256
#define DECAYF 0.9f
#define BETA_O 1.0f
#define BETA_S 1.0f

// ---- scratch (static device globals: no allocation) ----
__device__ float g_cosQ[D_RF * N_ST];   // 8 MB
__device__ float g_sinQ[D_RF * N_ST];   // 8 MB
__device__ float g_s0re[D_RF], g_s0im[D_RF];
__device__ float g_s2re[D_RF], g_s2im[D_RF];
__device__ float g_score[N_ST];         // raw scores (softmax replicated later)
__device__ float g_dotRe;
__device__ float g_obsacc[NOBS];

// ============================================================
// Kernel AB (fused): blocks [0,512): theta=W@Q tiles -> cos/sin tables
//                    blocks [512,2560): state0 = M @ obs  (row dot)
//                    side duty: zero-init accumulators for this step
// ============================================================
__global__ void __launch_bounds__(256) k_ab(
    const float* __restrict__ W, const float* __restrict__ Q,
    const float* __restrict__ M_re, const float* __restrict__ M_im,
    const float* __restrict__ obs)
{
    __shared__ float sh[2 * 16 * 68];   // Ws[16][68] + Qs[16][68]; also reduction scratch
    const int b   = blockIdx.x;
    const int tid = threadIdx.x;

    if (b < 512) {
        // ---- phi_Q GEMM: 64x64 tile, 256 threads, 4x4 micro-tile ----
        float (*Ws)[68] = (float(*)[68])sh;
        float (*Qs)[68] = (float(*)[68])(sh + 16 * 68);
        const int td = b >> 4, ts = b & 15;
        const int d0 = td * 64, s0 = ts * 64;
        const int tx = tid & 15, ty = tid >> 4;

        float acc[4][4];
        #pragma unroll
        for (int i = 0; i < 4; i++)
            #pragma unroll
            for (int j = 0; j < 4; j++) acc[i][j] = 0.f;

        const int wdl = tid >> 2, wkq = (tid & 3) * 4;   // W loader: 4 threads/row
        const int qk  = tid >> 4, qsq = (tid & 15) * 4;  // Q loader

        for (int k0 = 0; k0 < SDIM; k0 += 16) {
            float4 w4 = *(const float4*)&W[(size_t)(d0 + wdl) * SDIM + k0 + wkq];
            float4 q4 = *(const float4*)&Q[(size_t)(k0 + qk) * N_ST + s0 + qsq];
            __syncthreads();
            Ws[wkq + 0][wdl] = w4.x; Ws[wkq + 1][wdl] = w4.y;
            Ws[wkq + 2][wdl] = w4.z; Ws[wkq + 3][wdl] = w4.w;
            *(float4*)&Qs[qk][qsq] = q4;
            __syncthreads();
            #pragma unroll
            for (int k = 0; k < 16; k++) {
                float4 wv = *(float4*)&Ws[k][ty * 4];
                float4 qv = *(float4*)&Qs[k][tx * 4];
                float wa[4] = {wv.x, wv.y, wv.z, wv.w};
                float qa[4] = {qv.x, qv.y, qv.z, qv.w};
                #pragma unroll
                for (int i = 0; i < 4; i++)
                    #pragma unroll
                    for (int j = 0; j < 4; j++)
                        acc[i][j] = fmaf(wa[i], qa[j], acc[i][j]);
            }
        }
        // epilogue: sincos + float4 stores
        #pragma unroll
        for (int i = 0; i < 4; i++) {
            float c[4], s[4];
            #pragma unroll
            for (int j = 0; j < 4; j++) __sincosf(acc[i][j], &s[j], &c[j]);
            size_t base = (size_t)(d0 + ty * 4 + i) * N_ST + s0 + tx * 4;
            *(float4*)&g_cosQ[base] = make_float4(c[0], c[1], c[2], c[3]);
            *(float4*)&g_sinQ[base] = make_float4(s[0], s[1], s[2], s[3]);
        }
    } else {
        const int d = b - 512;  // row of M, 0..2047
        // zero-init side duties (safe: consumers run in later launches)
        if (d < 80) { int o = d * 256 + tid; if (o < NOBS) g_obsacc[o] = 0.f; }
        if (d < 4)  g_score[d * 256 + tid] = 0.f;
        if (d == 0 && tid == 0) g_dotRe = 0.f;

        const float4* mr = (const float4*)(M_re + (size_t)d * NOBS);
        const float4* mi = (const float4*)(M_im + (size_t)d * NOBS);
        const float4* ob = (const float4*)obs;
        float are = 0.f, aim = 0.f;
        #pragma unroll 4
        for (int i = tid; i < NOBS / 4; i += 256) {
            float4 o4 = ob[i]; float4 r4 = mr[i]; float4 i4 = mi[i];
            are += r4.x * o4.x + r4.y * o4.y + r4.z * o4.z + r4.w * o4.w;
            aim += i4.x * o4.x + i4.y * o4.y + i4.z * o4.z + i4.w * o4.w;
        }
        #pragma unroll
        for (int off = 16; off > 0; off >>= 1) {
            are += __shfl_down_sync(~0u, are, off);
            aim += __shfl_down_sync(~0u, aim, off);
        }
        const int w = tid >> 5, l = tid & 31;
        if (l == 0) { sh[w] = are; sh[8 + w] = aim; }
        __syncthreads();
        if (w == 0) {
            are = (l < 8) ? sh[l]     : 0.f;
            aim = (l < 8) ? sh[8 + l] : 0.f;
            #pragma unroll
            for (int off = 4; off > 0; off >>= 1) {
                are += __shfl_down_sync(~0u, are, off);
                aim += __shfl_down_sync(~0u, aim, off);
            }
            if (l == 0) { g_s0re[d] = are; g_s0im[d] = aim; }
        }
    }
}

// ============================================================
// Kernel SC (fused state1 + score):
//   128 blocks x 256 threads; block dc owns d-chunk [dc*16, dc*16+16).
//   Per block: v = V@action (dup), theta_v = W@v for 16 rows,
//   state1 = state0*exp(i theta_v) (smem only), then
//   score[s] += sum_dd cos*s1re + sin*s1im for all 1024 s (float4).
// ============================================================
__global__ void __launch_bounds__(256) k_score()
{
    __shared__ float vs[SDIM];
    __shared__ float s1r[16], s1i[16];
    const int tid = threadIdx.x;
    const int d0  = blockIdx.x * 16;
    const int w = tid >> 5, l = tid & 31;

    // v = V @ action  (V passed via constant pointers below)
    // (pointers provided through kernel args)
    extern __shared__ float dummy_unused[]; (void)dummy_unused;
    // -- filled in by wrapper (see launch): we pass V,W,action as params
    // placeholder; real body in k_score_impl
    (void)vs; (void)s1r; (void)s1i; (void)d0; (void)w; (void)l;
}

// real implementation with parameters
__global__ void __launch_bounds__(256) k_score_impl(
    const float* __restrict__ V, const float* __restrict__ W,
    const float* __restrict__ action)
{
    __shared__ float vs[SDIM];
    __shared__ float s1r[16], s1i[16];
    const int tid = threadIdx.x;
    const int d0  = blockIdx.x * 16;
    const int w = tid >> 5, l = tid & 31;

    // v[tid] = dot(V[tid,:], action)
    {
        float a = 0.f;
        const float* vr = V + tid * N_ACT;
        #pragma unroll 8
        for (int k = 0; k < N_ACT; k++) a = fmaf(vr[k], action[k], a);
        vs[tid] = a;
    }
    __syncthreads();

    // 8 warps, 2 rows each: theta = W[d,:] . v ; state1 = s0 * e^{i theta}
    #pragma unroll
    for (int r = 0; r < 2; r++) {
        const int dl = w * 2 + r;
        const int d  = d0 + dl;
        const float* wr = W + (size_t)d * SDIM;
        float t = 0.f;
        #pragma unroll
        for (int k = l; k < SDIM; k += 32) t = fmaf(wr[k], vs[k], t);
        #pragma unroll
        for (int off = 16; off > 0; off >>= 1) t += __shfl_down_sync(~0u, t, off);
        if (l == 0) {
            float sn, cs;
            sincosf(t, &sn, &cs);
            const float a = g_s0re[d], b = g_s0im[d];
            s1r[dl] = a * cs - b * sn;
            s1i[dl] = a * sn + b * cs;
        }
    }
    __syncthreads();

    // score accumulation: thread handles s = tid*4 .. tid*4+3 (float4)
    float4 acc = make_float4(0.f, 0.f, 0.f, 0.f);
    #pragma unroll
    for (int dd = 0; dd < 16; dd++) {
        const size_t row = (size_t)(d0 + dd) * N_ST + tid * 4;
        const float4 c4 = *(const float4*)&g_cosQ[row];
        const float4 n4 = *(const float4*)&g_sinQ[row];
        const float a = s1r[dd], b = s1i[dd];
        acc.x = fmaf(c4.x, a, fmaf(n4.x, b, acc.x));
        acc.y = fmaf(c4.y, a, fmaf(n4.y, b, acc.y));
        acc.z = fmaf(c4.z, a, fmaf(n4.z, b, acc.z));
        acc.w = fmaf(c4.w, a, fmaf(n4.w, b, acc.w));
    }
    const float sc = BETA_S / (float)D_RF;
    atomicAdd(&g_score[tid * 4 + 0], acc.x * sc);
    atomicAdd(&g_score[tid * 4 + 1], acc.y * sc);
    atomicAdd(&g_score[tid * 4 + 2], acc.z * sc);
    atomicAdd(&g_score[tid * 4 + 3], acc.w * sc);
}

// ============================================================
// Kernel F (fused softmax + state2):
//   256 blocks x 256 threads. Each block replicates softmax(score) -> smem,
//   then computes 8 rows of state2 = phi_Q @ weights (float4 loads),
//   plus atomic dotRe = Re(state0 . conj(state2)).
// ============================================================
__global__ void __launch_bounds__(256) k_state2()
{
    __shared__ __align__(16) float ws[N_ST];
    __shared__ float red[9];
    const int tid = threadIdx.x;
    const int w = tid >> 5, l = tid & 31;

    // load raw scores (4 per thread), block max
    float v0 = g_score[tid], v1 = g_score[tid + 256],
          v2 = g_score[tid + 512], v3 = g_score[tid + 768];
    float m = fmaxf(fmaxf(v0, v1), fmaxf(v2, v3));
    #pragma unroll
    for (int off = 16; off > 0; off >>= 1) m = fmaxf(m, __shfl_xor_sync(~0u, m, off));
    if (l == 0) red[w] = m;
    __syncthreads();
    if (tid < 32) {
        float t = (tid < 8) ? red[tid] : -1e30f;
        #pragma unroll
        for (int off = 4; off > 0; off >>= 1) t = fmaxf(t, __shfl_xor_sync(~0u, t, off));
        if (tid == 0) red[8] = t;
    }
    __syncthreads();
    const float mx = red[8];
    float e0 = __expf(v0 - mx), e1 = __expf(v1 - mx),
          e2 = __expf(v2 - mx), e3 = __expf(v3 - mx);
    float s = e0 + e1 + e2 + e3;
    __syncthreads();
    #pragma unroll
    for (int off = 16; off > 0; off >>= 1) s += __shfl_xor_sync(~0u, s, off);
    if (l == 0) red[w] = s;
    __syncthreads();
    if (tid < 32) {
        float t = (tid < 8) ? red[tid] : 0.f;
        #pragma unroll
        for (int off = 4; off > 0; off >>= 1) t += __shfl_xor_sync(~0u, t, off);
        if (tid == 0) red[8] = t;
    }
    __syncthreads();
    const float inv = 1.f / red[8];
    ws[tid]       = e0 * inv;
    ws[tid + 256] = e1 * inv;
    ws[tid + 512] = e2 * inv;
    ws[tid + 768] = e3 * inv;
    __syncthreads();

    // state2: warp per row, 8 rows/block, float4 loads
    const int d = blockIdx.x * 8 + w;
    const float* cr = g_cosQ + (size_t)d * N_ST;
    const float* si = g_sinQ + (size_t)d * N_ST;
    float ar = 0.f, ai = 0.f;
    #pragma unroll
    for (int j = 0; j < 8; j++) {
        const int s4 = (l + j * 32) * 4;
        const float4 c4 = *(const float4*)&cr[s4];
        const float4 n4 = *(const float4*)&si[s4];
        const float4 w4 = *(const float4*)&ws[s4];
        ar = fmaf(c4.x, w4.x, fmaf(c4.y, w4.y, fmaf(c4.z, w4.z, fmaf(c4.w, w4.w, ar))));
        ai = fmaf(n4.x, w4.x, fmaf(n4.y, w4.y, fmaf(n4.z, w4.z, fmaf(n4.w, w4.w, ai))));
    }
    #pragma unroll
    for (int off = 16; off > 0; off >>= 1) {
        ar += __shfl_down_sync(~0u, ar, off);
        ai += __shfl_down_sync(~0u, ai, off);
    }
    if (l == 0) {
        g_s2re[d] = ar; g_s2im[d] = ai;
        atomicAdd(&g_dotRe, g_s0re[d] * ar + g_s0im[d] * ai);
    }
}

// ============================================================
// Kernel H: obsacc[o] += sum_d M_re[d,o]*s2re[d] + M_im[d,o]*s2im[d]
// grid 320: 20 o-chunks (256 float4 = 1024 obs) x 16 d-chunks (128)
// ============================================================
__global__ void __launch_bounds__(256) k_obs(
    const float* __restrict__ M_re, const float* __restrict__ M_im)
{
    __shared__ float s2r[128], s2i[128];
    const int oc = blockIdx.x % 20, dc = blockIdx.x / 20;
    const int tid = threadIdx.x;
    const int d0 = dc * 128;
    if (tid < 128) { s2r[tid] = g_s2re[d0 + tid]; s2i[tid] = g_s2im[d0 + tid]; }
    __syncthreads();
    const int o4 = oc * 256 + tid;          // float4 index into the row
    if (o4 >= NOBS / 4) return;
    const float4* mr = (const float4*)M_re;
    const float4* mi = (const float4*)M_im;
    float4 acc = make_float4(0.f, 0.f, 0.f, 0.f);
    #pragma unroll 4
    for (int dd = 0; dd < 128; dd++) {
        const size_t row = (size_t)(d0 + dd) * (NOBS / 4) + o4;
        const float4 r = mr[row], im = mi[row];
        const float a = s2r[dd], b = s2i[dd];
        acc.x = fmaf(r.x, a, fmaf(im.x, b, acc.x));
        acc.y = fmaf(r.y, a, fmaf(im.y, b, acc.y));
        acc.z = fmaf(r.z, a, fmaf(im.z, b, acc.z));
        acc.w = fmaf(r.w, a, fmaf(im.w, b, acc.w));
    }
    atomicAdd(&g_obsacc[o4 * 4 + 0], acc.x);
    atomicAdd(&g_obsacc[o4 * 4 + 1], acc.y);
    atomicAdd(&g_obsacc[o4 * 4 + 2], acc.z);
    atomicAdd(&g_obsacc[o4 * 4 + 3], acc.w);
}

// ============================================================
// Kernel I: final = softmax( (BETA_O/D) * (DECAY*obsacc + obs*dotRe) )
// 1 block x 1024 threads, three passes over 20000 (L2-resident)
// ============================================================
__global__ void __launch_bounds__(1024) k_final(
    const float* __restrict__ obs, float* __restrict__ out)
{
    __shared__ float red[33];
    const int tid = threadIdx.x;
    const float dot   = g_dotRe;
    const float scale = BETA_O / (float)D_RF;

    float m = -1e30f;
    for (int i = tid; i < NOBS; i += 1024) {
        const float v = scale * (DECAYF * g_obsacc[i] + obs[i] * dot);
        g_obsacc[i] = v;
        m = fmaxf(m, v);
    }
    #pragma unroll
    for (int off = 16; off > 0; off >>= 1) m = fmaxf(m, __shfl_xor_sync(~0u, m, off));
    if ((tid & 31) == 0) red[tid >> 5] = m;
    __syncthreads();
    if (tid < 32) {
        float t = red[tid];
        #pragma unroll
        for (int off = 16; off > 0; off >>= 1) t = fmaxf(t, __shfl_xor_sync(~0u, t, off));
        if (tid == 0) red[32] = t;
    }
    __syncthreads();
    const float mx = red[32];
    __syncthreads();

    float s = 0.f;
    for (int i = tid; i < NOBS; i += 1024) {
        const float e = __expf(g_obsacc[i] - mx);
        g_obsacc[i] = e;
        s += e;
    }
    #pragma unroll
    for (int off = 16; off > 0; off >>= 1) s += __shfl_xor_sync(~0u, s, off);
    if ((tid & 31) == 0) red[tid >> 5] = s;
    __syncthreads();
    if (tid < 32) {
        float t = red[tid];
        #pragma unroll
        for (int off = 16; off > 0; off >>= 1) t += __shfl_xor_sync(~0u, t, off);
        if (tid == 0) red[32] = t;
    }
    __syncthreads();
    const float inv = 1.f / red[32];
    for (int i = tid; i < NOBS; i += 1024) out[i] = g_obsacc[i] * inv;
}

// ============================================================
extern "C" void kernel_launch(void* const* d_in, const int* in_sizes, int n_in,
                              void* d_out, int out_size)
{
    const float* Q      = (const float*)d_in[0];
    const float* V      = (const float*)d_in[1];
    const float* W      = (const float*)d_in[2];
    const float* M_re   = (const float*)d_in[3];
    const float* M_im   = (const float*)d_in[4];
    const float* obs    = (const float*)d_in[5];
    const float* action = (const float*)d_in[6];
    float* out = (float*)d_out;

    k_ab<<<2560, 256>>>(W, Q, M_re, M_im, obs);   // phi_Q tables + state0 + zero-init
    k_score_impl<<<128, 256>>>(V, W, action);     // state1 (smem) + score partials
    k_state2<<<256, 256>>>();                     // softmax + state2 + dotRe
    k_obs<<<320, 256>>>(M_re, M_im);              // M^T . conj(state2) partials
    k_final<<<1, 1024>>>(obs, out);               // combine + softmax -> out
}

// round 3
// speedup vs baseline: 1.1777x; 1.0037x over previous
#include <cuda_runtime.h>
#include <math.h>

#define D_RF   2048
#define NOBS   20000
#define N_ST   1024
#define N_ACT  64
#define SDIM   256
#define DECAYF 0.9f
#define BETA_O 1.0f
#define BETA_S 1.0f

// ---- scratch (static device globals: no allocation) ----
__device__ float g_cosQ[D_RF * N_ST];   // 8 MB
__device__ float g_sinQ[D_RF * N_ST];   // 8 MB
__device__ float g_s0re[D_RF], g_s0im[D_RF];
__device__ float g_s2re[D_RF], g_s2im[D_RF];
__device__ float g_score[N_ST];         // raw scores (softmax replicated later)
__device__ float g_dotRe;
__device__ float g_obsacc[NOBS];

// ============================================================
// Kernel AB (fused): blocks [0,512): theta=W@Q tiles -> cos/sin tables
//                    blocks [512,2560): state0 = M @ obs  (row dot)
//                    side duty: zero-init accumulators for this step
// ============================================================
__global__ void __launch_bounds__(256) k_ab(
    const float* __restrict__ W, const float* __restrict__ Q,
    const float* __restrict__ M_re, const float* __restrict__ M_im,
    const float* __restrict__ obs)
{
    __shared__ float sh[2 * 16 * 68];   // Ws[16][68] + Qs[16][68]; also reduction scratch
    const int b   = blockIdx.x;
    const int tid = threadIdx.x;

    if (b < 512) {
        // ---- phi_Q GEMM: 64x64 tile, 256 threads, 4x4 micro-tile ----
        float (*Ws)[68] = (float(*)[68])sh;
        float (*Qs)[68] = (float(*)[68])(sh + 16 * 68);
        const int td = b >> 4, ts = b & 15;
        const int d0 = td * 64, s0 = ts * 64;
        const int tx = tid & 15, ty = tid >> 4;

        float acc[4][4];
        #pragma unroll
        for (int i = 0; i < 4; i++)
            #pragma unroll
            for (int j = 0; j < 4; j++) acc[i][j] = 0.f;

        const int wdl = tid >> 2, wkq = (tid & 3) * 4;   // W loader: 4 threads/row
        const int qk  = tid >> 4, qsq = (tid & 15) * 4;  // Q loader

        for (int k0 = 0; k0 < SDIM; k0 += 16) {
            float4 w4 = *(const float4*)&W[(size_t)(d0 + wdl) * SDIM + k0 + wkq];
            float4 q4 = *(const float4*)&Q[(size_t)(k0 + qk) * N_ST + s0 + qsq];
            __syncthreads();
            Ws[wkq + 0][wdl] = w4.x; Ws[wkq + 1][wdl] = w4.y;
            Ws[wkq + 2][wdl] = w4.z; Ws[wkq + 3][wdl] = w4.w;
            *(float4*)&Qs[qk][qsq] = q4;
            __syncthreads();
            #pragma unroll
            for (int k = 0; k < 16; k++) {
                float4 wv = *(float4*)&Ws[k][ty * 4];
                float4 qv = *(float4*)&Qs[k][tx * 4];
                float wa[4] = {wv.x, wv.y, wv.z, wv.w};
                float qa[4] = {qv.x, qv.y, qv.z, qv.w};
                #pragma unroll
                for (int i = 0; i < 4; i++)
                    #pragma unroll
                    for (int j = 0; j < 4; j++)
                        acc[i][j] = fmaf(wa[i], qa[j], acc[i][j]);
            }
        }
        // epilogue: sincos + float4 stores
        #pragma unroll
        for (int i = 0; i < 4; i++) {
            float c[4], s[4];
            #pragma unroll
            for (int j = 0; j < 4; j++) __sincosf(acc[i][j], &s[j], &c[j]);
            size_t base = (size_t)(d0 + ty * 4 + i) * N_ST + s0 + tx * 4;
            *(float4*)&g_cosQ[base] = make_float4(c[0], c[1], c[2], c[3]);
            *(float4*)&g_sinQ[base] = make_float4(s[0], s[1], s[2], s[3]);
        }
    } else {
        const int d = b - 512;  // row of M, 0..2047
        // zero-init side duties (safe: consumers run in later launches)
        if (d < 80) { int o = d * 256 + tid; if (o < NOBS) g_obsacc[o] = 0.f; }
        if (d < 4)  g_score[d * 256 + tid] = 0.f;
        if (d == 0 && tid == 0) g_dotRe = 0.f;

        const float4* mr = (const float4*)(M_re + (size_t)d * NOBS);
        const float4* mi = (const float4*)(M_im + (size_t)d * NOBS);
        const float4* ob = (const float4*)obs;
        float are = 0.f, aim = 0.f;

        // MLP: batch 8 independent iterations' loads (16 float4 in flight)
        int i = tid;
        for (; i + 256 * 7 < NOBS / 4; i += 256 * 8) {
            float4 r[8], m4[8], o4[8];
            #pragma unroll
            for (int j = 0; j < 8; j++) {
                r[j]  = mr[i + 256 * j];
                m4[j] = mi[i + 256 * j];
                o4[j] = ob[i + 256 * j];
            }
            #pragma unroll
            for (int j = 0; j < 8; j++) {
                are = fmaf(r[j].x,  o4[j].x, fmaf(r[j].y,  o4[j].y,
                      fmaf(r[j].z,  o4[j].z, fmaf(r[j].w,  o4[j].w, are))));
                aim = fmaf(m4[j].x, o4[j].x, fmaf(m4[j].y, o4[j].y,
                      fmaf(m4[j].z, o4[j].z, fmaf(m4[j].w, o4[j].w, aim))));
            }
        }
        for (; i < NOBS / 4; i += 256) {
            float4 o4 = ob[i]; float4 r4 = mr[i]; float4 i4 = mi[i];
            are = fmaf(r4.x, o4.x, fmaf(r4.y, o4.y, fmaf(r4.z, o4.z, fmaf(r4.w, o4.w, are))));
            aim = fmaf(i4.x, o4.x, fmaf(i4.y, o4.y, fmaf(i4.z, o4.z, fmaf(i4.w, o4.w, aim))));
        }
        #pragma unroll
        for (int off = 16; off > 0; off >>= 1) {
            are += __shfl_down_sync(~0u, are, off);
            aim += __shfl_down_sync(~0u, aim, off);
        }
        const int w = tid >> 5, l = tid & 31;
        if (l == 0) { sh[w] = are; sh[8 + w] = aim; }
        __syncthreads();
        if (w == 0) {
            are = (l < 8) ? sh[l]     : 0.f;
            aim = (l < 8) ? sh[8 + l] : 0.f;
            #pragma unroll
            for (int off = 4; off > 0; off >>= 1) {
                are += __shfl_down_sync(~0u, are, off);
                aim += __shfl_down_sync(~0u, aim, off);
            }
            if (l == 0) { g_s0re[d] = are; g_s0im[d] = aim; }
        }
    }
}

// ============================================================
// Kernel SC (fused state1 + score):
//   128 blocks x 256 threads; block dc owns d-chunk [dc*16, dc*16+16).
//   Per block: v = V@action (dup), theta_v = W@v for 16 rows,
//   state1 = state0*exp(i theta_v) (smem only), then
//   score[s] += sum_dd cos*s1re + sin*s1im for all 1024 s (float4).
// ============================================================
__global__ void __launch_bounds__(256) k_score_impl(
    const float* __restrict__ V, const float* __restrict__ W,
    const float* __restrict__ action)
{
    __shared__ float vs[SDIM];
    __shared__ float s1r[16], s1i[16];
    const int tid = threadIdx.x;
    const int d0  = blockIdx.x * 16;
    const int w = tid >> 5, l = tid & 31;

    // v[tid] = dot(V[tid,:], action)
    {
        float a = 0.f;
        const float* vr = V + tid * N_ACT;
        #pragma unroll 8
        for (int k = 0; k < N_ACT; k++) a = fmaf(vr[k], action[k], a);
        vs[tid] = a;
    }
    __syncthreads();

    // 8 warps, 2 rows each: theta = W[d,:] . v ; state1 = s0 * e^{i theta}
    #pragma unroll
    for (int r = 0; r < 2; r++) {
        const int dl = w * 2 + r;
        const int d  = d0 + dl;
        const float* wr = W + (size_t)d * SDIM;
        float t = 0.f;
        #pragma unroll
        for (int k = l; k < SDIM; k += 32) t = fmaf(wr[k], vs[k], t);
        #pragma unroll
        for (int off = 16; off > 0; off >>= 1) t += __shfl_down_sync(~0u, t, off);
        if (l == 0) {
            float sn, cs;
            sincosf(t, &sn, &cs);
            const float a = g_s0re[d], b = g_s0im[d];
            s1r[dl] = a * cs - b * sn;
            s1i[dl] = a * sn + b * cs;
        }
    }
    __syncthreads();

    // score accumulation: thread handles s = tid*4 .. tid*4+3 (float4)
    float4 acc = make_float4(0.f, 0.f, 0.f, 0.f);
    #pragma unroll
    for (int dd = 0; dd < 16; dd++) {
        const size_t row = (size_t)(d0 + dd) * N_ST + tid * 4;
        const float4 c4 = *(const float4*)&g_cosQ[row];
        const float4 n4 = *(const float4*)&g_sinQ[row];
        const float a = s1r[dd], b = s1i[dd];
        acc.x = fmaf(c4.x, a, fmaf(n4.x, b, acc.x));
        acc.y = fmaf(c4.y, a, fmaf(n4.y, b, acc.y));
        acc.z = fmaf(c4.z, a, fmaf(n4.z, b, acc.z));
        acc.w = fmaf(c4.w, a, fmaf(n4.w, b, acc.w));
    }
    const float sc = BETA_S / (float)D_RF;
    atomicAdd(&g_score[tid * 4 + 0], acc.x * sc);
    atomicAdd(&g_score[tid * 4 + 1], acc.y * sc);
    atomicAdd(&g_score[tid * 4 + 2], acc.z * sc);
    atomicAdd(&g_score[tid * 4 + 3], acc.w * sc);
}

// ============================================================
// Kernel F (fused softmax + state2):
//   256 blocks x 256 threads. Each block replicates softmax(score) -> smem,
//   then computes 8 rows of state2 = phi_Q @ weights (float4 loads),
//   plus atomic dotRe = Re(state0 . conj(state2)).
// ============================================================
__global__ void __launch_bounds__(256) k_state2()
{
    __shared__ __align__(16) float ws[N_ST];
    __shared__ float red[9];
    const int tid = threadIdx.x;
    const int w = tid >> 5, l = tid & 31;

    // load raw scores (4 per thread), block max
    float v0 = g_score[tid], v1 = g_score[tid + 256],
          v2 = g_score[tid + 512], v3 = g_score[tid + 768];
    float m = fmaxf(fmaxf(v0, v1), fmaxf(v2, v3));
    #pragma unroll
    for (int off = 16; off > 0; off >>= 1) m = fmaxf(m, __shfl_xor_sync(~0u, m, off));
    if (l == 0) red[w] = m;
    __syncthreads();
    if (tid < 32) {
        float t = (tid < 8) ? red[tid] : -1e30f;
        #pragma unroll
        for (int off = 4; off > 0; off >>= 1) t = fmaxf(t, __shfl_xor_sync(~0u, t, off));
        if (tid == 0) red[8] = t;
    }
    __syncthreads();
    const float mx = red[8];
    float e0 = __expf(v0 - mx), e1 = __expf(v1 - mx),
          e2 = __expf(v2 - mx), e3 = __expf(v3 - mx);
    float s = e0 + e1 + e2 + e3;
    __syncthreads();
    #pragma unroll
    for (int off = 16; off > 0; off >>= 1) s += __shfl_xor_sync(~0u, s, off);
    if (l == 0) red[w] = s;
    __syncthreads();
    if (tid < 32) {
        float t = (tid < 8) ? red[tid] : 0.f;
        #pragma unroll
        for (int off = 4; off > 0; off >>= 1) t += __shfl_xor_sync(~0u, t, off);
        if (tid == 0) red[8] = t;
    }
    __syncthreads();
    const float inv = 1.f / red[8];
    ws[tid]       = e0 * inv;
    ws[tid + 256] = e1 * inv;
    ws[tid + 512] = e2 * inv;
    ws[tid + 768] = e3 * inv;
    __syncthreads();

    // state2: warp per row, 8 rows/block, float4 loads
    const int d = blockIdx.x * 8 + w;
    const float* cr = g_cosQ + (size_t)d * N_ST;
    const float* si = g_sinQ + (size_t)d * N_ST;
    float ar = 0.f, ai = 0.f;
    #pragma unroll
    for (int j = 0; j < 8; j++) {
        const int s4 = (l + j * 32) * 4;
        const float4 c4 = *(const float4*)&cr[s4];
        const float4 n4 = *(const float4*)&si[s4];
        const float4 w4 = *(const float4*)&ws[s4];
        ar = fmaf(c4.x, w4.x, fmaf(c4.y, w4.y, fmaf(c4.z, w4.z, fmaf(c4.w, w4.w, ar))));
        ai = fmaf(n4.x, w4.x, fmaf(n4.y, w4.y, fmaf(n4.z, w4.z, fmaf(n4.w, w4.w, ai))));
    }
    #pragma unroll
    for (int off = 16; off > 0; off >>= 1) {
        ar += __shfl_down_sync(~0u, ar, off);
        ai += __shfl_down_sync(~0u, ai, off);
    }
    if (l == 0) {
        g_s2re[d] = ar; g_s2im[d] = ai;
        atomicAdd(&g_dotRe, g_s0re[d] * ar + g_s0im[d] * ai);
    }
}

// ============================================================
// Kernel H: obsacc[o] += sum_d M_re[d,o]*s2re[d] + M_im[d,o]*s2im[d]
// grid 1280: 20 o-chunks (256 float4 = 1024 obs) x 64 d-chunks (32 rows)
// High occupancy (8+ blocks/SM) => enough in-flight loads for DRAM roof.
// ============================================================
__global__ void __launch_bounds__(256) k_obs(
    const float* __restrict__ M_re, const float* __restrict__ M_im)
{
    __shared__ float s2r[32], s2i[32];
    const int oc = blockIdx.x % 20, dc = blockIdx.x / 20;
    const int tid = threadIdx.x;
    const int d0 = dc * 32;
    if (tid < 32) { s2r[tid] = g_s2re[d0 + tid]; s2i[tid] = g_s2im[d0 + tid]; }
    __syncthreads();
    const int o4 = oc * 256 + tid;          // float4 index into the row
    if (o4 >= NOBS / 4) return;
    const float4* mr = (const float4*)M_re;
    const float4* mi = (const float4*)M_im;
    float4 acc = make_float4(0.f, 0.f, 0.f, 0.f);
    #pragma unroll
    for (int d8 = 0; d8 < 32; d8 += 8) {
        float4 r[8], im[8];
        #pragma unroll
        for (int j = 0; j < 8; j++) {
            const size_t row = (size_t)(d0 + d8 + j) * (NOBS / 4) + o4;
            r[j]  = mr[row];
            im[j] = mi[row];
        }
        #pragma unroll
        for (int j = 0; j < 8; j++) {
            const float a = s2r[d8 + j], b = s2i[d8 + j];
            acc.x = fmaf(r[j].x, a, fmaf(im[j].x, b, acc.x));
            acc.y = fmaf(r[j].y, a, fmaf(im[j].y, b, acc.y));
            acc.z = fmaf(r[j].z, a, fmaf(im[j].z, b, acc.z));
            acc.w = fmaf(r[j].w, a, fmaf(im[j].w, b, acc.w));
        }
    }
    atomicAdd(&g_obsacc[o4 * 4 + 0], acc.x);
    atomicAdd(&g_obsacc[o4 * 4 + 1], acc.y);
    atomicAdd(&g_obsacc[o4 * 4 + 2], acc.z);
    atomicAdd(&g_obsacc[o4 * 4 + 3], acc.w);
}

// ============================================================
// Kernel I: final = softmax( (BETA_O/D) * (DECAY*obsacc + obs*dotRe) )
// 1 block x 1024 threads, three passes over 20000 (L2-resident)
// ============================================================
__global__ void __launch_bounds__(1024) k_final(
    const float* __restrict__ obs, float* __restrict__ out)
{
    __shared__ float red[33];
    const int tid = threadIdx.x;
    const float dot   = g_dotRe;
    const float scale = BETA_O / (float)D_RF;

    float m = -1e30f;
    for (int i = tid; i < NOBS; i += 1024) {
        const float v = scale * (DECAYF * g_obsacc[i] + obs[i] * dot);
        g_obsacc[i] = v;
        m = fmaxf(m, v);
    }
    #pragma unroll
    for (int off = 16; off > 0; off >>= 1) m = fmaxf(m, __shfl_xor_sync(~0u, m, off));
    if ((tid & 31) == 0) red[tid >> 5] = m;
    __syncthreads();
    if (tid < 32) {
        float t = red[tid];
        #pragma unroll
        for (int off = 16; off > 0; off >>= 1) t = fmaxf(t, __shfl_xor_sync(~0u, t, off));
        if (tid == 0) red[32] = t;
    }
    __syncthreads();
    const float mx = red[32];
    __syncthreads();

    float s = 0.f;
    for (int i = tid; i < NOBS; i += 1024) {
        const float e = __expf(g_obsacc[i] - mx);
        g_obsacc[i] = e;
        s += e;
    }
    #pragma unroll
    for (int off = 16; off > 0; off >>= 1) s += __shfl_xor_sync(~0u, s, off);
    if ((tid & 31) == 0) red[tid >> 5] = s;
    __syncthreads();
    if (tid < 32) {
        float t = red[tid];
        #pragma unroll
        for (int off = 16; off > 0; off >>= 1) t += __shfl_xor_sync(~0u, t, off);
        if (tid == 0) red[32] = t;
    }
    __syncthreads();
    const float inv = 1.f / red[32];
    for (int i = tid; i < NOBS; i += 1024) out[i] = g_obsacc[i] * inv;
}

// ============================================================
extern "C" void kernel_launch(void* const* d_in, const int* in_sizes, int n_in,
                              void* d_out, int out_size)
{
    const float* Q      = (const float*)d_in[0];
    const float* V      = (const float*)d_in[1];
    const float* W      = (const float*)d_in[2];
    const float* M_re   = (const float*)d_in[3];
    const float* M_im   = (const float*)d_in[4];
    const float* obs    = (const float*)d_in[5];
    const float* action = (const float*)d_in[6];
    float* out = (float*)d_out;

    k_ab<<<2560, 256>>>(W, Q, M_re, M_im, obs);   // phi_Q tables + state0 + zero-init
    k_score_impl<<<128, 256>>>(V, W, action);     // state1 (smem) + score partials
    k_state2<<<256, 256>>>();                     // softmax + state2 + dotRe
    k_obs<<<1280, 256>>>(M_re, M_im);             // M^T . conj(state2) partials
    k_final<<<1, 1024>>>(obs, out);               // combine + softmax -> out
}

// round 4
// speedup vs baseline: 1.2206x; 1.0364x over previous
#include <cuda_runtime.h>
#include <math.h>

#define D_RF   2048
#define NOBS   20000
#define N_ST   1024
#define N_ACT  64
#define SDIM   256
#define DECAYF 0.9f
#define BETA_O 1.0f
#define BETA_S 1.0f

// ---- scratch (static device globals: no allocation) ----
__device__ float g_cosQ[D_RF * N_ST];   // 8 MB
__device__ float g_sinQ[D_RF * N_ST];   // 8 MB
__device__ float g_s0re[D_RF], g_s0im[D_RF];
__device__ float g_s2re[D_RF], g_s2im[D_RF];
__device__ float g_score[N_ST];         // raw scores (softmax replicated later)
__device__ float g_dotRe;
__device__ float g_obsacc[NOBS];

// ============================================================
// Kernel AB (fused): blocks [0,512): theta=W@Q tiles -> cos/sin tables
//                    blocks [512,1024): state0 = M @ obs, 4 rows per block
//                    side duty: zero-init accumulators for this step
// ============================================================
__global__ void __launch_bounds__(256) k_ab(
    const float* __restrict__ W, const float* __restrict__ Q,
    const float* __restrict__ M_re, const float* __restrict__ M_im,
    const float* __restrict__ obs)
{
    __shared__ float sh[2 * 16 * 68];   // GEMM tiles / M-half reduction scratch (8704B)
    const int b   = blockIdx.x;
    const int tid = threadIdx.x;

    if (b < 512) {
        // ---- phi_Q GEMM: 64x64 tile, 256 threads, 4x4 micro-tile ----
        float (*Ws)[68] = (float(*)[68])sh;
        float (*Qs)[68] = (float(*)[68])(sh + 16 * 68);
        const int td = b >> 4, ts = b & 15;
        const int d0 = td * 64, s0 = ts * 64;
        const int tx = tid & 15, ty = tid >> 4;

        float acc[4][4];
        #pragma unroll
        for (int i = 0; i < 4; i++)
            #pragma unroll
            for (int j = 0; j < 4; j++) acc[i][j] = 0.f;

        const int wdl = tid >> 2, wkq = (tid & 3) * 4;   // W loader: 4 threads/row
        const int qk  = tid >> 4, qsq = (tid & 15) * 4;  // Q loader

        for (int k0 = 0; k0 < SDIM; k0 += 16) {
            float4 w4 = *(const float4*)&W[(size_t)(d0 + wdl) * SDIM + k0 + wkq];
            float4 q4 = *(const float4*)&Q[(size_t)(k0 + qk) * N_ST + s0 + qsq];
            __syncthreads();
            Ws[wkq + 0][wdl] = w4.x; Ws[wkq + 1][wdl] = w4.y;
            Ws[wkq + 2][wdl] = w4.z; Ws[wkq + 3][wdl] = w4.w;
            *(float4*)&Qs[qk][qsq] = q4;
            __syncthreads();
            #pragma unroll
            for (int k = 0; k < 16; k++) {
                float4 wv = *(float4*)&Ws[k][ty * 4];
                float4 qv = *(float4*)&Qs[k][tx * 4];
                float wa[4] = {wv.x, wv.y, wv.z, wv.w};
                float qa[4] = {qv.x, qv.y, qv.z, qv.w};
                #pragma unroll
                for (int i = 0; i < 4; i++)
                    #pragma unroll
                    for (int j = 0; j < 4; j++)
                        acc[i][j] = fmaf(wa[i], qa[j], acc[i][j]);
            }
        }
        // epilogue: sincos + float4 stores
        #pragma unroll
        for (int i = 0; i < 4; i++) {
            float c[4], s[4];
            #pragma unroll
            for (int j = 0; j < 4; j++) __sincosf(acc[i][j], &s[j], &c[j]);
            size_t base = (size_t)(d0 + ty * 4 + i) * N_ST + s0 + tx * 4;
            *(float4*)&g_cosQ[base] = make_float4(c[0], c[1], c[2], c[3]);
            *(float4*)&g_sinQ[base] = make_float4(s[0], s[1], s[2], s[3]);
        }
    } else {
        const int mb = b - 512;          // 0..511, owns rows 4*mb .. 4*mb+3
        const int d0 = mb * 4;
        // zero-init side duties (consumers run in later launches)
        if (mb < 80) { int o = mb * 256 + tid; if (o < NOBS) g_obsacc[o] = 0.f; }
        if (mb < 4)  g_score[mb * 256 + tid] = 0.f;
        if (mb == 0 && tid == 0) g_dotRe = 0.f;

        const float4* mr = (const float4*)M_re;
        const float4* mi = (const float4*)M_im;
        const float4* ob = (const float4*)obs;

        float are[4] = {0.f, 0.f, 0.f, 0.f};
        float aim[4] = {0.f, 0.f, 0.f, 0.f};

        for (int i = tid; i < NOBS / 4; i += 256) {
            const float4 o4 = ob[i];
            float4 r[4], m4[4];
            #pragma unroll
            for (int rr = 0; rr < 4; rr++) {
                const size_t row = (size_t)(d0 + rr) * (NOBS / 4) + i;
                r[rr]  = __ldcs(&mr[row]);
                m4[rr] = __ldcs(&mi[row]);
            }
            #pragma unroll
            for (int rr = 0; rr < 4; rr++) {
                are[rr] = fmaf(r[rr].x,  o4.x, fmaf(r[rr].y,  o4.y,
                          fmaf(r[rr].z,  o4.z, fmaf(r[rr].w,  o4.w, are[rr]))));
                aim[rr] = fmaf(m4[rr].x, o4.x, fmaf(m4[rr].y, o4.y,
                          fmaf(m4[rr].z, o4.z, fmaf(m4[rr].w, o4.w, aim[rr]))));
            }
        }
        // block reduction: 8 components (4 rows x re/im) via smem
        #pragma unroll
        for (int rr = 0; rr < 4; rr++) {
            sh[(rr * 2 + 0) * 256 + tid] = are[rr];
            sh[(rr * 2 + 1) * 256 + tid] = aim[rr];
        }
        __syncthreads();
        const int w = tid >> 5, l = tid & 31;
        // warp w reduces component w over 256 entries
        float v = 0.f;
        #pragma unroll
        for (int k = 0; k < 8; k++) v += sh[w * 256 + l + k * 32];
        #pragma unroll
        for (int off = 16; off > 0; off >>= 1) v += __shfl_down_sync(~0u, v, off);
        if (l == 0) {
            const int rr = w >> 1, comp = w & 1;
            if (comp == 0) g_s0re[d0 + rr] = v;
            else           g_s0im[d0 + rr] = v;
        }
    }
}

// ============================================================
// Kernel SC (fused state1 + score):
//   256 blocks x 256 threads; block dc owns d-chunk [dc*8, dc*8+8).
//   Per block: v = V@action (dup), theta_v = W@v for 8 rows,
//   state1 = state0*exp(i theta_v) (smem only), then
//   score[s] += sum_dd cos*s1re + sin*s1im for all 1024 s (float4).
// ============================================================
__global__ void __launch_bounds__(256) k_score_impl(
    const float* __restrict__ V, const float* __restrict__ W,
    const float* __restrict__ action)
{
    __shared__ float vs[SDIM];
    __shared__ float s1r[8], s1i[8];
    const int tid = threadIdx.x;
    const int d0  = blockIdx.x * 8;
    const int w = tid >> 5, l = tid & 31;

    // v[tid] = dot(V[tid,:], action)
    {
        float a = 0.f;
        const float* vr = V + tid * N_ACT;
        #pragma unroll 8
        for (int k = 0; k < N_ACT; k++) a = fmaf(vr[k], action[k], a);
        vs[tid] = a;
    }
    __syncthreads();

    // 8 warps, 1 row each: theta = W[d,:] . v ; state1 = s0 * e^{i theta}
    {
        const int d = d0 + w;
        const float* wr = W + (size_t)d * SDIM;
        float t = 0.f;
        #pragma unroll
        for (int k = l; k < SDIM; k += 32) t = fmaf(wr[k], vs[k], t);
        #pragma unroll
        for (int off = 16; off > 0; off >>= 1) t += __shfl_down_sync(~0u, t, off);
        if (l == 0) {
            float sn, cs;
            sincosf(t, &sn, &cs);
            const float a = g_s0re[d], bb = g_s0im[d];
            s1r[w] = a * cs - bb * sn;
            s1i[w] = a * sn + bb * cs;
        }
    }
    __syncthreads();

    // score accumulation: thread handles s = tid*4 .. tid*4+3 (float4)
    float4 acc = make_float4(0.f, 0.f, 0.f, 0.f);
    #pragma unroll
    for (int dd = 0; dd < 8; dd++) {
        const size_t row = (size_t)(d0 + dd) * N_ST + tid * 4;
        const float4 c4 = *(const float4*)&g_cosQ[row];
        const float4 n4 = *(const float4*)&g_sinQ[row];
        const float a = s1r[dd], bb = s1i[dd];
        acc.x = fmaf(c4.x, a, fmaf(n4.x, bb, acc.x));
        acc.y = fmaf(c4.y, a, fmaf(n4.y, bb, acc.y));
        acc.z = fmaf(c4.z, a, fmaf(n4.z, bb, acc.z));
        acc.w = fmaf(c4.w, a, fmaf(n4.w, bb, acc.w));
    }
    const float sc = BETA_S / (float)D_RF;
    atomicAdd(&g_score[tid * 4 + 0], acc.x * sc);
    atomicAdd(&g_score[tid * 4 + 1], acc.y * sc);
    atomicAdd(&g_score[tid * 4 + 2], acc.z * sc);
    atomicAdd(&g_score[tid * 4 + 3], acc.w * sc);
}

// ============================================================
// Kernel F (fused softmax + state2):
//   512 blocks x 256 threads. Each block replicates softmax(score) -> smem,
//   then computes 4 rows of state2 (2 warps per row, split s-range),
//   plus atomic dotRe = Re(state0 . conj(state2)).
// ============================================================
__global__ void __launch_bounds__(256) k_state2()
{
    __shared__ __align__(16) float ws[N_ST];
    __shared__ float red[9];
    __shared__ float2 parts[8];
    const int tid = threadIdx.x;
    const int w = tid >> 5, l = tid & 31;

    // load raw scores (4 per thread), block max
    float v0 = g_score[tid], v1 = g_score[tid + 256],
          v2 = g_score[tid + 512], v3 = g_score[tid + 768];
    float m = fmaxf(fmaxf(v0, v1), fmaxf(v2, v3));
    #pragma unroll
    for (int off = 16; off > 0; off >>= 1) m = fmaxf(m, __shfl_xor_sync(~0u, m, off));
    if (l == 0) red[w] = m;
    __syncthreads();
    if (tid < 32) {
        float t = (tid < 8) ? red[tid] : -1e30f;
        #pragma unroll
        for (int off = 4; off > 0; off >>= 1) t = fmaxf(t, __shfl_xor_sync(~0u, t, off));
        if (tid == 0) red[8] = t;
    }
    __syncthreads();
    const float mx = red[8];
    float e0 = __expf(v0 - mx), e1 = __expf(v1 - mx),
          e2 = __expf(v2 - mx), e3 = __expf(v3 - mx);
    float s = e0 + e1 + e2 + e3;
    __syncthreads();
    #pragma unroll
    for (int off = 16; off > 0; off >>= 1) s += __shfl_xor_sync(~0u, s, off);
    if (l == 0) red[w] = s;
    __syncthreads();
    if (tid < 32) {
        float t = (tid < 8) ? red[tid] : 0.f;
        #pragma unroll
        for (int off = 4; off > 0; off >>= 1) t += __shfl_xor_sync(~0u, t, off);
        if (tid == 0) red[8] = t;
    }
    __syncthreads();
    const float inv = 1.f / red[8];
    ws[tid]       = e0 * inv;
    ws[tid + 256] = e1 * inv;
    ws[tid + 512] = e2 * inv;
    ws[tid + 768] = e3 * inv;
    __syncthreads();

    // state2: 2 warps per row (split s-range), 4 rows/block, float4 loads
    const int d    = blockIdx.x * 4 + (w >> 1);
    const int half = w & 1;                   // s in [half*512, half*512+512)
    const float* cr = g_cosQ + (size_t)d * N_ST;
    const float* si = g_sinQ + (size_t)d * N_ST;
    float ar = 0.f, ai = 0.f;
    #pragma unroll
    for (int j = 0; j < 4; j++) {
        const int s4 = half * 512 + (l + j * 32) * 4;
        const float4 c4 = *(const float4*)&cr[s4];
        const float4 n4 = *(const float4*)&si[s4];
        const float4 w4 = *(const float4*)&ws[s4];
        ar = fmaf(c4.x, w4.x, fmaf(c4.y, w4.y, fmaf(c4.z, w4.z, fmaf(c4.w, w4.w, ar))));
        ai = fmaf(n4.x, w4.x, fmaf(n4.y, w4.y, fmaf(n4.z, w4.z, fmaf(n4.w, w4.w, ai))));
    }
    #pragma unroll
    for (int off = 16; off > 0; off >>= 1) {
        ar += __shfl_down_sync(~0u, ar, off);
        ai += __shfl_down_sync(~0u, ai, off);
    }
    if (l == 0) parts[w] = make_float2(ar, ai);
    __syncthreads();
    if (tid < 4) {
        const int dd = blockIdx.x * 4 + tid;
        const float rr = parts[tid * 2].x + parts[tid * 2 + 1].x;
        const float ii = parts[tid * 2].y + parts[tid * 2 + 1].y;
        g_s2re[dd] = rr; g_s2im[dd] = ii;
        atomicAdd(&g_dotRe, g_s0re[dd] * rr + g_s0im[dd] * ii);
    }
}

// ============================================================
// Kernel H: obsacc[o] += sum_d M_re[d,o]*s2re[d] + M_im[d,o]*s2im[d]
// grid 1280: 20 o-chunks (256 float4 = 1024 obs) x 64 d-chunks (32 rows)
// ============================================================
__global__ void __launch_bounds__(256) k_obs(
    const float* __restrict__ M_re, const float* __restrict__ M_im)
{
    __shared__ float s2r[32], s2i[32];
    const int oc = blockIdx.x % 20, dc = blockIdx.x / 20;
    const int tid = threadIdx.x;
    const int d0 = dc * 32;
    if (tid < 32) { s2r[tid] = g_s2re[d0 + tid]; s2i[tid] = g_s2im[d0 + tid]; }
    __syncthreads();
    const int o4 = oc * 256 + tid;          // float4 index into the row
    if (o4 >= NOBS / 4) return;
    const float4* mr = (const float4*)M_re;
    const float4* mi = (const float4*)M_im;
    float4 acc = make_float4(0.f, 0.f, 0.f, 0.f);
    #pragma unroll
    for (int d8 = 0; d8 < 32; d8 += 8) {
        float4 r[8], im[8];
        #pragma unroll
        for (int j = 0; j < 8; j++) {
            const size_t row = (size_t)(d0 + d8 + j) * (NOBS / 4) + o4;
            r[j]  = __ldcs(&mr[row]);
            im[j] = __ldcs(&mi[row]);
        }
        #pragma unroll
        for (int j = 0; j < 8; j++) {
            const float a = s2r[d8 + j], b = s2i[d8 + j];
            acc.x = fmaf(r[j].x, a, fmaf(im[j].x, b, acc.x));
            acc.y = fmaf(r[j].y, a, fmaf(im[j].y, b, acc.y));
            acc.z = fmaf(r[j].z, a, fmaf(im[j].z, b, acc.z));
            acc.w = fmaf(r[j].w, a, fmaf(im[j].w, b, acc.w));
        }
    }
    atomicAdd(&g_obsacc[o4 * 4 + 0], acc.x);
    atomicAdd(&g_obsacc[o4 * 4 + 1], acc.y);
    atomicAdd(&g_obsacc[o4 * 4 + 2], acc.z);
    atomicAdd(&g_obsacc[o4 * 4 + 3], acc.w);
}

// ============================================================
// Kernel I: final = softmax( (BETA_O/D) * (DECAY*obsacc + obs*dotRe) )
// 1 block x 1024 threads, three passes over 20000 (L2-resident)
// ============================================================
__global__ void __launch_bounds__(1024) k_final(
    const float* __restrict__ obs, float* __restrict__ out)
{
    __shared__ float red[33];
    const int tid = threadIdx.x;
    const float dot   = g_dotRe;
    const float scale = BETA_O / (float)D_RF;

    float m = -1e30f;
    for (int i = tid; i < NOBS; i += 1024) {
        const float v = scale * (DECAYF * g_obsacc[i] + obs[i] * dot);
        g_obsacc[i] = v;
        m = fmaxf(m, v);
    }
    #pragma unroll
    for (int off = 16; off > 0; off >>= 1) m = fmaxf(m, __shfl_xor_sync(~0u, m, off));
    if ((tid & 31) == 0) red[tid >> 5] = m;
    __syncthreads();
    if (tid < 32) {
        float t = red[tid];
        #pragma unroll
        for (int off = 16; off > 0; off >>= 1) t = fmaxf(t, __shfl_xor_sync(~0u, t, off));
        if (tid == 0) red[32] = t;
    }
    __syncthreads();
    const float mx = red[32];
    __syncthreads();

    float s = 0.f;
    for (int i = tid; i < NOBS; i += 1024) {
        const float e = __expf(g_obsacc[i] - mx);
        g_obsacc[i] = e;
        s += e;
    }
    #pragma unroll
    for (int off = 16; off > 0; off >>= 1) s += __shfl_xor_sync(~0u, s, off);
    if ((tid & 31) == 0) red[tid >> 5] = s;
    __syncthreads();
    if (tid < 32) {
        float t = red[tid];
        #pragma unroll
        for (int off = 16; off > 0; off >>= 1) t += __shfl_xor_sync(~0u, t, off);
        if (tid == 0) red[32] = t;
    }
    __syncthreads();
    const float inv = 1.f / red[32];
    for (int i = tid; i < NOBS; i += 1024) out[i] = g_obsacc[i] * inv;
}

// ============================================================
extern "C" void kernel_launch(void* const* d_in, const int* in_sizes, int n_in,
                              void* d_out, int out_size)
{
    const float* Q      = (const float*)d_in[0];
    const float* V      = (const float*)d_in[1];
    const float* W      = (const float*)d_in[2];
    const float* M_re   = (const float*)d_in[3];
    const float* M_im   = (const float*)d_in[4];
    const float* obs    = (const float*)d_in[5];
    const float* action = (const float*)d_in[6];
    float* out = (float*)d_out;

    k_ab<<<1024, 256>>>(W, Q, M_re, M_im, obs);   // phi_Q tables + state0 + zero-init
    k_score_impl<<<256, 256>>>(V, W, action);     // state1 (smem) + score partials
    k_state2<<<512, 256>>>();                     // softmax + state2 + dotRe
    k_obs<<<1280, 256>>>(M_re, M_im);             // M^T . conj(state2) partials
    k_final<<<1, 1024>>>(obs, out);               // combine + softmax -> out
}